// round 1
// baseline (speedup 1.0000x reference)
#include <cuda_runtime.h>
#include <cstdint>

#define N_RES 768
#define C_M   256
#define C_Z   128
#define NO_BINS 15
#define EPS 1e-5f
#define INF_F 1e8f

// ---------------------------------------------------------------------------
// z kernel: one warp per (i,j) pair. 128 channels -> float4 per lane.
// out_z[p*128 + c] = d_emb(bin(d2(i,j)))[c] + b_lin[c]
//                  + (z[p,c]-mu)*rsqrt(var+eps)*g_z[c] + be_z[c]
// ---------------------------------------------------------------------------
__global__ __launch_bounds__(256, 8)
void z_update_kernel(const float* __restrict__ z,
                     const float* __restrict__ x,
                     const float* __restrict__ w_lin,   // [C_Z, NO_BINS]
                     const float* __restrict__ b_lin,   // [C_Z]
                     const float* __restrict__ g_z,     // [C_Z]
                     const float* __restrict__ be_z,    // [C_Z]
                     float* __restrict__ out_z)
{
    const unsigned warp = (blockIdx.x * blockDim.x + threadIdx.x) >> 5;
    const unsigned lane = threadIdx.x & 31u;
    if (warp >= (unsigned)(N_RES * N_RES)) return;

    const unsigned i = warp / N_RES;
    const unsigned j = warp - i * N_RES;

    // --- load row of z (fully coalesced, 128B per warp-quarter) ---
    const float4* zrow = reinterpret_cast<const float4*>(z + (size_t)warp * C_Z);
    float4 v = zrow[lane];

    // --- warp layernorm stats ---
    float s  = v.x + v.y + v.z + v.w;
    float sq = v.x * v.x + v.y * v.y + v.z * v.z + v.w * v.w;
    #pragma unroll
    for (int off = 16; off > 0; off >>= 1) {
        s  += __shfl_xor_sync(0xffffffffu, s,  off);
        sq += __shfl_xor_sync(0xffffffffu, sq, off);
    }
    const float mean = s * (1.0f / C_Z);
    const float var  = sq * (1.0f / C_Z) - mean * mean;
    const float inv  = rsqrtf(var + EPS);

    // --- squared distance (broadcast loads; x is tiny and L1-hot) ---
    const float dx = __ldg(&x[i * 3 + 0]) - __ldg(&x[j * 3 + 0]);
    const float dy = __ldg(&x[i * 3 + 1]) - __ldg(&x[j * 3 + 1]);
    const float dz = __ldg(&x[i * 3 + 2]) - __ldg(&x[j * 3 + 2]);
    const float d2 = dx * dx + dy * dy + dz * dz;

    // --- bin select: bins = 3.25 + 1.25k, all exactly representable ---
    int b = -1;
    #pragma unroll
    for (int k = 0; k < NO_BINS; k++) {
        const float bk = 3.25f + 1.25f * (float)k;       // const-folded
        const float lo = bk * bk;
        const float bk1 = 3.25f + 1.25f * (float)(k + 1);
        const float hi = (k < NO_BINS - 1) ? bk1 * bk1 : INF_F;
        if (d2 > lo && d2 < hi) b = k;
    }

    // --- per-lane channel params (L1-hot broadcast tables) ---
    const int c = lane * 4;
    const float4 g  = *reinterpret_cast<const float4*>(g_z  + c);
    const float4 be = *reinterpret_cast<const float4*>(be_z + c);
    const float4 bl = *reinterpret_cast<const float4*>(b_lin + c);

    float e0 = 0.f, e1 = 0.f, e2 = 0.f, e3 = 0.f;
    if (b >= 0) {
        e0 = __ldg(&w_lin[(c + 0) * NO_BINS + b]);
        e1 = __ldg(&w_lin[(c + 1) * NO_BINS + b]);
        e2 = __ldg(&w_lin[(c + 2) * NO_BINS + b]);
        e3 = __ldg(&w_lin[(c + 3) * NO_BINS + b]);
    }

    float4 o;
    o.x = e0 + bl.x + (v.x - mean) * inv * g.x + be.x;
    o.y = e1 + bl.y + (v.y - mean) * inv * g.y + be.y;
    o.z = e2 + bl.z + (v.z - mean) * inv * g.z + be.z;
    o.w = e3 + bl.w + (v.w - mean) * inv * g.w + be.w;

    reinterpret_cast<float4*>(out_z + (size_t)warp * C_Z)[lane] = o;
}

// ---------------------------------------------------------------------------
// m kernel: one warp per row of 256 channels (2 float4 per lane).
// ---------------------------------------------------------------------------
__global__ __launch_bounds__(256, 8)
void m_update_kernel(const float* __restrict__ m,
                     const float* __restrict__ g_m,
                     const float* __restrict__ be_m,
                     float* __restrict__ out_m)
{
    const unsigned warp = (blockIdx.x * blockDim.x + threadIdx.x) >> 5;
    const unsigned lane = threadIdx.x & 31u;
    if (warp >= (unsigned)N_RES) return;

    const float4* mrow = reinterpret_cast<const float4*>(m + (size_t)warp * C_M);
    float4 a = mrow[lane];
    float4 b = mrow[lane + 32];

    float s  = a.x + a.y + a.z + a.w + b.x + b.y + b.z + b.w;
    float sq = a.x*a.x + a.y*a.y + a.z*a.z + a.w*a.w
             + b.x*b.x + b.y*b.y + b.z*b.z + b.w*b.w;
    #pragma unroll
    for (int off = 16; off > 0; off >>= 1) {
        s  += __shfl_xor_sync(0xffffffffu, s,  off);
        sq += __shfl_xor_sync(0xffffffffu, sq, off);
    }
    const float mean = s * (1.0f / C_M);
    const float var  = sq * (1.0f / C_M) - mean * mean;
    const float inv  = rsqrtf(var + EPS);

    const int c0 = lane * 4;
    const int c1 = (lane + 32) * 4;
    const float4 g0  = *reinterpret_cast<const float4*>(g_m  + c0);
    const float4 be0 = *reinterpret_cast<const float4*>(be_m + c0);
    const float4 g1  = *reinterpret_cast<const float4*>(g_m  + c1);
    const float4 be1 = *reinterpret_cast<const float4*>(be_m + c1);

    float4 oa, ob;
    oa.x = (a.x - mean) * inv * g0.x + be0.x;
    oa.y = (a.y - mean) * inv * g0.y + be0.y;
    oa.z = (a.z - mean) * inv * g0.z + be0.z;
    oa.w = (a.w - mean) * inv * g0.w + be0.w;
    ob.x = (b.x - mean) * inv * g1.x + be1.x;
    ob.y = (b.y - mean) * inv * g1.y + be1.y;
    ob.z = (b.z - mean) * inv * g1.z + be1.z;
    ob.w = (b.w - mean) * inv * g1.w + be1.w;

    float4* orow = reinterpret_cast<float4*>(out_m + (size_t)warp * C_M);
    orow[lane]      = oa;
    orow[lane + 32] = ob;
}

// ---------------------------------------------------------------------------
// Inputs (metadata order): m, z, x, w_lin, b_lin, g_m, be_m, g_z, be_z
// Output: concat(flatten(m_update), flatten(z_update))
// ---------------------------------------------------------------------------
extern "C" void kernel_launch(void* const* d_in, const int* in_sizes, int n_in,
                              void* d_out, int out_size)
{
    const float* m     = (const float*)d_in[0];
    const float* z     = (const float*)d_in[1];
    const float* x     = (const float*)d_in[2];
    const float* w_lin = (const float*)d_in[3];
    const float* b_lin = (const float*)d_in[4];
    const float* g_m   = (const float*)d_in[5];
    const float* be_m  = (const float*)d_in[6];
    const float* g_z   = (const float*)d_in[7];
    const float* be_z  = (const float*)d_in[8];

    float* out_m = (float*)d_out;
    float* out_z = out_m + (size_t)N_RES * C_M;

    // m: 768 rows, 1 warp each -> 96 blocks of 256 threads
    m_update_kernel<<<(N_RES * 32 + 255) / 256, 256>>>(m, g_m, be_m, out_m);

    // z: 768*768 pairs, 1 warp each -> 73728 blocks of 256 threads
    const int n_pairs = N_RES * N_RES;
    z_update_kernel<<<(n_pairs * 32 + 255) / 256, 256>>>(
        z, x, w_lin, b_lin, g_z, be_z, out_z);
}

// round 2
// speedup vs baseline: 1.3577x; 1.3577x over previous
#include <cuda_runtime.h>
#include <cstdint>

#define N_RES 768
#define C_M   256
#define C_Z   128
#define NO_BINS 15
#define EPS 1e-5f
#define INF_F 1e8f

// Fused per-bin embedding table: fused[bin][c] = w_lin[c][bin] + b_lin[c] + be_z[c]
// Row 15 = "no bin hit" = b_lin[c] + be_z[c].
__device__ float g_fused_table[16 * C_Z];

// ---------------------------------------------------------------------------
// m kernel (+ fused-table build in extra blocks).
// Blocks [0, 96): one warp per m row (8 warps/block).
// Blocks [96, 112): block b builds fused table row (b - 96).
// ---------------------------------------------------------------------------
__global__ __launch_bounds__(256)
void m_and_table_kernel(const float* __restrict__ m,
                        const float* __restrict__ g_m,
                        const float* __restrict__ be_m,
                        const float* __restrict__ w_lin,   // [C_Z, NO_BINS]
                        const float* __restrict__ b_lin,   // [C_Z]
                        const float* __restrict__ be_z,    // [C_Z]
                        float* __restrict__ out_m)
{
    if (blockIdx.x >= (N_RES / 8)) {
        // ---- table build ----
        const int bin = blockIdx.x - (N_RES / 8);   // 0..15
        const int c = threadIdx.x;
        if (c < C_Z) {
            float v = b_lin[c] + be_z[c];
            if (bin < NO_BINS) v += w_lin[c * NO_BINS + bin];
            g_fused_table[bin * C_Z + c] = v;
        }
        return;
    }

    const unsigned warp = (blockIdx.x * blockDim.x + threadIdx.x) >> 5;
    const unsigned lane = threadIdx.x & 31u;

    const float4* mrow = reinterpret_cast<const float4*>(m + (size_t)warp * C_M);
    float4 a = mrow[lane];
    float4 b = mrow[lane + 32];

    float s  = a.x + a.y + a.z + a.w + b.x + b.y + b.z + b.w;
    float sq = a.x*a.x + a.y*a.y + a.z*a.z + a.w*a.w
             + b.x*b.x + b.y*b.y + b.z*b.z + b.w*b.w;
    #pragma unroll
    for (int off = 16; off > 0; off >>= 1) {
        s  += __shfl_xor_sync(0xffffffffu, s,  off);
        sq += __shfl_xor_sync(0xffffffffu, sq, off);
    }
    const float mean = s * (1.0f / C_M);
    const float var  = sq * (1.0f / C_M) - mean * mean;
    const float inv  = rsqrtf(var + EPS);

    const int c0 = lane * 4;
    const int c1 = (lane + 32) * 4;
    const float4 g0  = *reinterpret_cast<const float4*>(g_m  + c0);
    const float4 be0 = *reinterpret_cast<const float4*>(be_m + c0);
    const float4 g1  = *reinterpret_cast<const float4*>(g_m  + c1);
    const float4 be1 = *reinterpret_cast<const float4*>(be_m + c1);

    float4 oa, ob;
    oa.x = (a.x - mean) * inv * g0.x + be0.x;
    oa.y = (a.y - mean) * inv * g0.y + be0.y;
    oa.z = (a.z - mean) * inv * g0.z + be0.z;
    oa.w = (a.w - mean) * inv * g0.w + be0.w;
    ob.x = (b.x - mean) * inv * g1.x + be1.x;
    ob.y = (b.y - mean) * inv * g1.y + be1.y;
    ob.z = (b.z - mean) * inv * g1.z + be1.z;
    ob.w = (b.w - mean) * inv * g1.w + be1.w;

    float4* orow = reinterpret_cast<float4*>(out_m + (size_t)warp * C_M);
    orow[lane]      = oa;
    orow[lane + 32] = ob;
}

// ---------------------------------------------------------------------------
// z kernel: one warp per 2 consecutive (i,j) pairs (same i since 768 is even).
// Streaming loads/stores; fused embedding table lookup (1 float4 per lane).
// ---------------------------------------------------------------------------
__global__ __launch_bounds__(256, 6)
void z_update_kernel(const float* __restrict__ z,
                     const float* __restrict__ x,
                     const float* __restrict__ g_z,
                     float* __restrict__ out_z)
{
    const unsigned warp = (blockIdx.x * blockDim.x + threadIdx.x) >> 5;
    const unsigned lane = threadIdx.x & 31u;
    const unsigned p0 = warp * 2u;                 // pair index of first row
    if (p0 >= (unsigned)(N_RES * N_RES)) return;

    const unsigned i  = p0 / N_RES;
    const unsigned j0 = p0 - i * N_RES;            // even -> j0+1 stays in row i

    // --- front-batched streaming loads of 2 z rows ---
    const float4* zr0 = reinterpret_cast<const float4*>(z + (size_t)p0 * C_Z);
    const float4* zr1 = reinterpret_cast<const float4*>(z + (size_t)(p0 + 1) * C_Z);
    float4 v0 = __ldcs(zr0 + lane);
    float4 v1 = __ldcs(zr1 + lane);

    // --- layernorm stats for both rows (shuffles carry 4 values) ---
    float s0  = v0.x + v0.y + v0.z + v0.w;
    float q0  = v0.x*v0.x + v0.y*v0.y + v0.z*v0.z + v0.w*v0.w;
    float s1  = v1.x + v1.y + v1.z + v1.w;
    float q1  = v1.x*v1.x + v1.y*v1.y + v1.z*v1.z + v1.w*v1.w;
    #pragma unroll
    for (int off = 16; off > 0; off >>= 1) {
        s0 += __shfl_xor_sync(0xffffffffu, s0, off);
        q0 += __shfl_xor_sync(0xffffffffu, q0, off);
        s1 += __shfl_xor_sync(0xffffffffu, s1, off);
        q1 += __shfl_xor_sync(0xffffffffu, q1, off);
    }
    const float mean0 = s0 * (1.0f / C_Z);
    const float inv0  = rsqrtf(q0 * (1.0f / C_Z) - mean0 * mean0 + EPS);
    const float mean1 = s1 * (1.0f / C_Z);
    const float inv1  = rsqrtf(q1 * (1.0f / C_Z) - mean1 * mean1 + EPS);

    // --- squared distances for j0, j0+1 (x is tiny, L1-hot) ---
    const float xi0 = __ldg(&x[i * 3 + 0]);
    const float xi1 = __ldg(&x[i * 3 + 1]);
    const float xi2 = __ldg(&x[i * 3 + 2]);
    const float a0x = xi0 - __ldg(&x[j0 * 3 + 0]);
    const float a0y = xi1 - __ldg(&x[j0 * 3 + 1]);
    const float a0z = xi2 - __ldg(&x[j0 * 3 + 2]);
    const float a1x = xi0 - __ldg(&x[(j0 + 1) * 3 + 0]);
    const float a1y = xi1 - __ldg(&x[(j0 + 1) * 3 + 1]);
    const float a1z = xi2 - __ldg(&x[(j0 + 1) * 3 + 2]);
    const float d20 = a0x*a0x + a0y*a0y + a0z*a0z;
    const float d21 = a1x*a1x + a1y*a1y + a1z*a1z;

    // --- bin select (bins 3.25 + 1.25k exactly representable) ---
    int b0 = 15, b1 = 15;
    #pragma unroll
    for (int k = 0; k < NO_BINS; k++) {
        const float bk  = 3.25f + 1.25f * (float)k;
        const float lo  = bk * bk;
        const float bk1 = 3.25f + 1.25f * (float)(k + 1);
        const float hi  = (k < NO_BINS - 1) ? bk1 * bk1 : INF_F;
        if (d20 > lo && d20 < hi) b0 = k;
        if (d21 > lo && d21 < hi) b1 = k;
    }

    // --- fused (emb + b_lin + be_z) rows + gamma: coalesced L1-hot loads ---
    const int c = lane * 4;
    const float4 f0 = *reinterpret_cast<const float4*>(g_fused_table + b0 * C_Z + c);
    const float4 f1 = *reinterpret_cast<const float4*>(g_fused_table + b1 * C_Z + c);
    const float4 g  = *reinterpret_cast<const float4*>(g_z + c);

    float4 o0, o1;
    o0.x = f0.x + (v0.x - mean0) * inv0 * g.x;
    o0.y = f0.y + (v0.y - mean0) * inv0 * g.y;
    o0.z = f0.z + (v0.z - mean0) * inv0 * g.z;
    o0.w = f0.w + (v0.w - mean0) * inv0 * g.w;
    o1.x = f1.x + (v1.x - mean1) * inv1 * g.x;
    o1.y = f1.y + (v1.y - mean1) * inv1 * g.y;
    o1.z = f1.z + (v1.z - mean1) * inv1 * g.z;
    o1.w = f1.w + (v1.w - mean1) * inv1 * g.w;

    __stcs(reinterpret_cast<float4*>(out_z + (size_t)p0 * C_Z) + lane, o0);
    __stcs(reinterpret_cast<float4*>(out_z + (size_t)(p0 + 1) * C_Z) + lane, o1);
}

// ---------------------------------------------------------------------------
// Inputs (metadata order): m, z, x, w_lin, b_lin, g_m, be_m, g_z, be_z
// Output: concat(flatten(m_update), flatten(z_update))
// ---------------------------------------------------------------------------
extern "C" void kernel_launch(void* const* d_in, const int* in_sizes, int n_in,
                              void* d_out, int out_size)
{
    const float* m     = (const float*)d_in[0];
    const float* z     = (const float*)d_in[1];
    const float* x     = (const float*)d_in[2];
    const float* w_lin = (const float*)d_in[3];
    const float* b_lin = (const float*)d_in[4];
    const float* g_m   = (const float*)d_in[5];
    const float* be_m  = (const float*)d_in[6];
    const float* g_z   = (const float*)d_in[7];
    const float* be_z  = (const float*)d_in[8];

    float* out_m = (float*)d_out;
    float* out_z = out_m + (size_t)N_RES * C_M;

    // 96 m-blocks + 16 table-build blocks (stream-ordered before z kernel)
    m_and_table_kernel<<<N_RES / 8 + 16, 256>>>(m, g_m, be_m, w_lin, b_lin, be_z, out_m);

    // z: 768*768 pairs, 2 per warp, 8 warps per block
    const int n_warps = (N_RES * N_RES) / 2;
    z_update_kernel<<<n_warps / 8, 256>>>(z, x, g_z, out_z);
}

// round 3
// speedup vs baseline: 1.4442x; 1.0637x over previous
#include <cuda_runtime.h>
#include <cstdint>

#define N_RES 768
#define C_M   256
#define C_Z   128
#define NO_BINS 15
#define EPS 1e-5f

// Fused per-bin embedding table: fused[bin][c] = w_lin[c][bin] + b_lin[c] + be_z[c]
// Row 15 = "no bin hit" = b_lin[c] + be_z[c].
__device__ float g_fused_table[16 * C_Z];

// Squared bin edges (3.25 + 1.25k)^2 — exactly representable in fp32.
#define E0  10.5625f
#define E1  20.25f
#define E2  33.0625f
#define E3  49.0f
#define E4  68.0625f
#define E5  90.25f
#define E6  115.5625f
#define E7  144.0f
#define E8  175.5625f
#define E9  210.25f
#define E10 248.0625f
#define E11 289.0f
#define E12 333.0625f
#define E13 380.25f
#define E14 430.5625f

// ---------------------------------------------------------------------------
// m kernel (+ fused-table build in extra blocks).
// ---------------------------------------------------------------------------
__global__ __launch_bounds__(256)
void m_and_table_kernel(const float* __restrict__ m,
                        const float* __restrict__ g_m,
                        const float* __restrict__ be_m,
                        const float* __restrict__ w_lin,   // [C_Z, NO_BINS]
                        const float* __restrict__ b_lin,   // [C_Z]
                        const float* __restrict__ be_z,    // [C_Z]
                        float* __restrict__ out_m)
{
    if (blockIdx.x >= (N_RES / 8)) {
        const int bin = blockIdx.x - (N_RES / 8);   // 0..15
        const int c = threadIdx.x;
        if (c < C_Z) {
            float v = b_lin[c] + be_z[c];
            if (bin < NO_BINS) v += w_lin[c * NO_BINS + bin];
            g_fused_table[bin * C_Z + c] = v;
        }
        return;
    }

    const unsigned warp = (blockIdx.x * blockDim.x + threadIdx.x) >> 5;
    const unsigned lane = threadIdx.x & 31u;

    const float4* mrow = reinterpret_cast<const float4*>(m + (size_t)warp * C_M);
    float4 a = mrow[lane];
    float4 b = mrow[lane + 32];

    float s  = a.x + a.y + a.z + a.w + b.x + b.y + b.z + b.w;
    float sq = a.x*a.x + a.y*a.y + a.z*a.z + a.w*a.w
             + b.x*b.x + b.y*b.y + b.z*b.z + b.w*b.w;
    #pragma unroll
    for (int off = 16; off > 0; off >>= 1) {
        s  += __shfl_xor_sync(0xffffffffu, s,  off);
        sq += __shfl_xor_sync(0xffffffffu, sq, off);
    }
    const float mean = s * (1.0f / C_M);
    const float var  = sq * (1.0f / C_M) - mean * mean;
    const float inv  = rsqrtf(var + EPS);

    const int c0 = lane * 4;
    const int c1 = (lane + 32) * 4;
    const float4 g0  = *reinterpret_cast<const float4*>(g_m  + c0);
    const float4 be0 = *reinterpret_cast<const float4*>(be_m + c0);
    const float4 g1  = *reinterpret_cast<const float4*>(g_m  + c1);
    const float4 be1 = *reinterpret_cast<const float4*>(be_m + c1);

    float4 oa, ob;
    oa.x = (a.x - mean) * inv * g0.x + be0.x;
    oa.y = (a.y - mean) * inv * g0.y + be0.y;
    oa.z = (a.z - mean) * inv * g0.z + be0.z;
    oa.w = (a.w - mean) * inv * g0.w + be0.w;
    ob.x = (b.x - mean) * inv * g1.x + be1.x;
    ob.y = (b.y - mean) * inv * g1.y + be1.y;
    ob.z = (b.z - mean) * inv * g1.z + be1.z;
    ob.w = (b.w - mean) * inv * g1.w + be1.w;

    float4* orow = reinterpret_cast<float4*>(out_m + (size_t)warp * C_M);
    orow[lane]      = oa;
    orow[lane + 32] = ob;
}

// ---------------------------------------------------------------------------
// z kernel: one warp per 32 consecutive (i,j) pairs (all same i: 32 | 768).
// Phase A: each lane computes the distogram bin for ONE pair.
// Phase B: stream the 32 rows, 4 per iteration; bins via shuffle broadcast.
// ---------------------------------------------------------------------------
__global__ __launch_bounds__(256)
void z_update_kernel(const float* __restrict__ z,
                     const float* __restrict__ x,
                     const float* __restrict__ g_z,
                     float* __restrict__ out_z)
{
    const unsigned warp = (blockIdx.x * blockDim.x + threadIdx.x) >> 5;
    const unsigned lane = threadIdx.x & 31u;
    const unsigned row_base = warp * 32u;           // first pair index
    const unsigned i = row_base / N_RES;            // constant across 32 pairs
    const unsigned j = (row_base - i * N_RES) + lane;

    // ---- Phase A: bin for pair (i, j) in this lane ----
    const float dx = __ldg(&x[i * 3 + 0]) - __ldg(&x[j * 3 + 0]);
    const float dy = __ldg(&x[i * 3 + 1]) - __ldg(&x[j * 3 + 1]);
    const float dz = __ldg(&x[i * 3 + 2]) - __ldg(&x[j * 3 + 2]);
    const float d2 = dx * dx + dy * dy + dz * dz;

    int c = 0;
    c += (d2 > E0);  c += (d2 > E1);  c += (d2 > E2);  c += (d2 > E3);
    c += (d2 > E4);  c += (d2 > E5);  c += (d2 > E6);  c += (d2 > E7);
    c += (d2 > E8);  c += (d2 > E9);  c += (d2 > E10); c += (d2 > E11);
    c += (d2 > E12); c += (d2 > E13); c += (d2 > E14);
    const int mybin = (c == 0) ? 15 : (c - 1);      // 15 = no-bin row

    // ---- per-warp invariants ----
    const float4 g = *reinterpret_cast<const float4*>(g_z + lane * 4);
    const float4* zb = reinterpret_cast<const float4*>(z + (size_t)row_base * C_Z) + lane;
    float4*       ob = reinterpret_cast<float4*>(out_z + (size_t)row_base * C_Z) + lane;
    const float* ft = g_fused_table + lane * 4;

    // ---- Phase B: stream 32 rows, 4 per iteration ----
    #pragma unroll 2
    for (int r = 0; r < 32; r += 4) {
        // front-batched streaming loads (imm offsets off one base)
        float4 v0 = __ldcs(zb + (r + 0) * 32);
        float4 v1 = __ldcs(zb + (r + 1) * 32);
        float4 v2 = __ldcs(zb + (r + 2) * 32);
        float4 v3 = __ldcs(zb + (r + 3) * 32);

        float s0 = v0.x + v0.y + v0.z + v0.w;
        float q0 = v0.x*v0.x + v0.y*v0.y + v0.z*v0.z + v0.w*v0.w;
        float s1 = v1.x + v1.y + v1.z + v1.w;
        float q1 = v1.x*v1.x + v1.y*v1.y + v1.z*v1.z + v1.w*v1.w;
        float s2 = v2.x + v2.y + v2.z + v2.w;
        float q2 = v2.x*v2.x + v2.y*v2.y + v2.z*v2.z + v2.w*v2.w;
        float s3 = v3.x + v3.y + v3.z + v3.w;
        float q3 = v3.x*v3.x + v3.y*v3.y + v3.z*v3.z + v3.w*v3.w;

        #pragma unroll
        for (int off = 16; off > 0; off >>= 1) {
            s0 += __shfl_xor_sync(0xffffffffu, s0, off);
            q0 += __shfl_xor_sync(0xffffffffu, q0, off);
            s1 += __shfl_xor_sync(0xffffffffu, s1, off);
            q1 += __shfl_xor_sync(0xffffffffu, q1, off);
            s2 += __shfl_xor_sync(0xffffffffu, s2, off);
            q2 += __shfl_xor_sync(0xffffffffu, q2, off);
            s3 += __shfl_xor_sync(0xffffffffu, s3, off);
            q3 += __shfl_xor_sync(0xffffffffu, q3, off);
        }

        const float m0 = s0 * (1.0f / C_Z);
        const float i0 = rsqrtf(q0 * (1.0f / C_Z) - m0 * m0 + EPS);
        const float m1 = s1 * (1.0f / C_Z);
        const float i1 = rsqrtf(q1 * (1.0f / C_Z) - m1 * m1 + EPS);
        const float m2 = s2 * (1.0f / C_Z);
        const float i2 = rsqrtf(q2 * (1.0f / C_Z) - m2 * m2 + EPS);
        const float m3 = s3 * (1.0f / C_Z);
        const float i3 = rsqrtf(q3 * (1.0f / C_Z) - m3 * m3 + EPS);

        const int b0 = __shfl_sync(0xffffffffu, mybin, r + 0);
        const int b1 = __shfl_sync(0xffffffffu, mybin, r + 1);
        const int b2 = __shfl_sync(0xffffffffu, mybin, r + 2);
        const int b3 = __shfl_sync(0xffffffffu, mybin, r + 3);

        const float4 f0 = *reinterpret_cast<const float4*>(ft + b0 * C_Z);
        const float4 f1 = *reinterpret_cast<const float4*>(ft + b1 * C_Z);
        const float4 f2 = *reinterpret_cast<const float4*>(ft + b2 * C_Z);
        const float4 f3 = *reinterpret_cast<const float4*>(ft + b3 * C_Z);

        float4 o0, o1, o2, o3;
        o0.x = f0.x + (v0.x - m0) * i0 * g.x;
        o0.y = f0.y + (v0.y - m0) * i0 * g.y;
        o0.z = f0.z + (v0.z - m0) * i0 * g.z;
        o0.w = f0.w + (v0.w - m0) * i0 * g.w;
        o1.x = f1.x + (v1.x - m1) * i1 * g.x;
        o1.y = f1.y + (v1.y - m1) * i1 * g.y;
        o1.z = f1.z + (v1.z - m1) * i1 * g.z;
        o1.w = f1.w + (v1.w - m1) * i1 * g.w;
        o2.x = f2.x + (v2.x - m2) * i2 * g.x;
        o2.y = f2.y + (v2.y - m2) * i2 * g.y;
        o2.z = f2.z + (v2.z - m2) * i2 * g.z;
        o2.w = f2.w + (v2.w - m2) * i2 * g.w;
        o3.x = f3.x + (v3.x - m3) * i3 * g.x;
        o3.y = f3.y + (v3.y - m3) * i3 * g.y;
        o3.z = f3.z + (v3.z - m3) * i3 * g.z;
        o3.w = f3.w + (v3.w - m3) * i3 * g.w;

        __stcs(ob + (r + 0) * 32, o0);
        __stcs(ob + (r + 1) * 32, o1);
        __stcs(ob + (r + 2) * 32, o2);
        __stcs(ob + (r + 3) * 32, o3);
    }
}

// ---------------------------------------------------------------------------
// Inputs (metadata order): m, z, x, w_lin, b_lin, g_m, be_m, g_z, be_z
// Output: concat(flatten(m_update), flatten(z_update))
// ---------------------------------------------------------------------------
extern "C" void kernel_launch(void* const* d_in, const int* in_sizes, int n_in,
                              void* d_out, int out_size)
{
    const float* m     = (const float*)d_in[0];
    const float* z     = (const float*)d_in[1];
    const float* x     = (const float*)d_in[2];
    const float* w_lin = (const float*)d_in[3];
    const float* b_lin = (const float*)d_in[4];
    const float* g_m   = (const float*)d_in[5];
    const float* be_m  = (const float*)d_in[6];
    const float* g_z   = (const float*)d_in[7];
    const float* be_z  = (const float*)d_in[8];

    float* out_m = (float*)d_out;
    float* out_z = out_m + (size_t)N_RES * C_M;

    // 96 m-blocks + 16 table-build blocks (stream-ordered before z kernel)
    m_and_table_kernel<<<N_RES / 8 + 16, 256>>>(m, g_m, be_m, w_lin, b_lin, be_z, out_m);

    // z: 768*768 pairs, 32 per warp, 8 warps per block
    const int n_warps = (N_RES * N_RES) / 32;   // 18432
    z_update_kernel<<<n_warps / 8, 256>>>(z, x, g_z, out_z);
}

// round 4
// speedup vs baseline: 1.4495x; 1.0037x over previous
#include <cuda_runtime.h>
#include <cstdint>

#define N_RES 768
#define C_M   256
#define C_Z   128
#define NO_BINS 15
#define EPS 1e-5f

#define NZBLOCKS 2304          // (768*768/32 pairs-per-warp) / 8 warps-per-block
#define NMBLOCKS 96            // 768 m-rows / 8 warps

// Squared bin edges (3.25 + 1.25k)^2 — exactly representable in fp32.
#define E0  10.5625f
#define E1  20.25f
#define E2  33.0625f
#define E3  49.0f
#define E4  68.0625f
#define E5  90.25f
#define E6  115.5625f
#define E7  144.0f
#define E8  175.5625f
#define E9  210.25f
#define E10 248.0625f
#define E11 289.0f
#define E12 333.0625f
#define E13 380.25f
#define E14 430.5625f

__global__ __launch_bounds__(256, 4)
void fused_kernel(const float* __restrict__ z,
                  const float* __restrict__ x,
                  const float* __restrict__ g_z,
                  const float* __restrict__ m,
                  const float* __restrict__ g_m,
                  const float* __restrict__ be_m,
                  const float* __restrict__ w_lin,   // [C_Z, NO_BINS]
                  const float* __restrict__ b_lin,   // [C_Z]
                  const float* __restrict__ be_z,    // [C_Z]
                  float* __restrict__ out_m,
                  float* __restrict__ out_z)
{
    const unsigned lane = threadIdx.x & 31u;

    // =====================================================================
    // m-layernorm path: blocks [NZBLOCKS, NZBLOCKS+NMBLOCKS)
    // =====================================================================
    if (blockIdx.x >= NZBLOCKS) {
        const unsigned row = (blockIdx.x - NZBLOCKS) * 8u + ((threadIdx.x) >> 5);

        const float4* mrow = reinterpret_cast<const float4*>(m + (size_t)row * C_M);
        float4 a = mrow[lane];
        float4 b = mrow[lane + 32];

        float s  = a.x + a.y + a.z + a.w + b.x + b.y + b.z + b.w;
        float sq = a.x*a.x + a.y*a.y + a.z*a.z + a.w*a.w
                 + b.x*b.x + b.y*b.y + b.z*b.z + b.w*b.w;
        #pragma unroll
        for (int off = 16; off > 0; off >>= 1) {
            s  += __shfl_xor_sync(0xffffffffu, s,  off);
            sq += __shfl_xor_sync(0xffffffffu, sq, off);
        }
        const float mean = s * (1.0f / C_M);
        const float inv  = rsqrtf(sq * (1.0f / C_M) - mean * mean + EPS);

        const int c0 = lane * 4;
        const int c1 = (lane + 32) * 4;
        const float4 g0  = *reinterpret_cast<const float4*>(g_m  + c0);
        const float4 be0 = *reinterpret_cast<const float4*>(be_m + c0);
        const float4 g1  = *reinterpret_cast<const float4*>(g_m  + c1);
        const float4 be1 = *reinterpret_cast<const float4*>(be_m + c1);

        float4 oa, ob;
        oa.x = (a.x - mean) * inv * g0.x + be0.x;
        oa.y = (a.y - mean) * inv * g0.y + be0.y;
        oa.z = (a.z - mean) * inv * g0.z + be0.z;
        oa.w = (a.w - mean) * inv * g0.w + be0.w;
        ob.x = (b.x - mean) * inv * g1.x + be1.x;
        ob.y = (b.y - mean) * inv * g1.y + be1.y;
        ob.z = (b.z - mean) * inv * g1.z + be1.z;
        ob.w = (b.w - mean) * inv * g1.w + be1.w;

        float4* orow = reinterpret_cast<float4*>(out_m + (size_t)row * C_M);
        orow[lane]      = oa;
        orow[lane + 32] = ob;
        return;
    }

    // =====================================================================
    // z path: one warp per 32 consecutive (i,j) pairs (same i: 32 | 768).
    // =====================================================================
    // Fused per-bin table in SMEM: ft[bin][c] = w_lin[c][bin] + b_lin[c] + be_z[c]
    // Row 15 = "no bin" = b_lin + be_z.
    __shared__ float ft_s[16 * C_Z];
    #pragma unroll
    for (int idx = threadIdx.x; idx < 16 * C_Z; idx += 256) {
        const int bin = idx >> 7;
        const int ch  = idx & 127;
        float v = b_lin[ch] + be_z[ch];
        if (bin < NO_BINS) v += w_lin[ch * NO_BINS + bin];
        ft_s[idx] = v;
    }
    __syncthreads();

    const unsigned warp = blockIdx.x * 8u + (threadIdx.x >> 5);
    const unsigned row_base = warp * 32u;
    const unsigned i = row_base / N_RES;
    const unsigned j = (row_base - i * N_RES) + lane;

    // ---- Phase A: this lane's pair bin ----
    const float dx = __ldg(&x[i * 3 + 0]) - __ldg(&x[j * 3 + 0]);
    const float dy = __ldg(&x[i * 3 + 1]) - __ldg(&x[j * 3 + 1]);
    const float dz = __ldg(&x[i * 3 + 2]) - __ldg(&x[j * 3 + 2]);
    const float d2 = dx * dx + dy * dy + dz * dz;

    int cnt = 0;
    cnt += (d2 > E0);  cnt += (d2 > E1);  cnt += (d2 > E2);  cnt += (d2 > E3);
    cnt += (d2 > E4);  cnt += (d2 > E5);  cnt += (d2 > E6);  cnt += (d2 > E7);
    cnt += (d2 > E8);  cnt += (d2 > E9);  cnt += (d2 > E10); cnt += (d2 > E11);
    cnt += (d2 > E12); cnt += (d2 > E13); cnt += (d2 > E14);
    const int mybin = (cnt == 0) ? 15 : (cnt - 1);

    // ---- per-warp invariants ----
    const float4 g = *reinterpret_cast<const float4*>(g_z + lane * 4);
    const float4* zb = reinterpret_cast<const float4*>(z + (size_t)row_base * C_Z) + lane;
    float4*       obp = reinterpret_cast<float4*>(out_z + (size_t)row_base * C_Z) + lane;
    const float* ft = ft_s + lane * 4;

    // ---- Phase B: stream 32 rows, 4/iter, double-buffered ----
    float4 v0 = __ldcs(zb + 0 * 32);
    float4 v1 = __ldcs(zb + 1 * 32);
    float4 v2 = __ldcs(zb + 2 * 32);
    float4 v3 = __ldcs(zb + 3 * 32);

    #pragma unroll
    for (int r = 0; r < 32; r += 4) {
        // prefetch next group while current is being reduced
        float4 n0, n1, n2, n3;
        if (r + 4 < 32) {
            n0 = __ldcs(zb + (r + 4) * 32);
            n1 = __ldcs(zb + (r + 5) * 32);
            n2 = __ldcs(zb + (r + 6) * 32);
            n3 = __ldcs(zb + (r + 7) * 32);
        }

        float s0 = v0.x + v0.y + v0.z + v0.w;
        float q0 = v0.x*v0.x + v0.y*v0.y + v0.z*v0.z + v0.w*v0.w;
        float s1 = v1.x + v1.y + v1.z + v1.w;
        float q1 = v1.x*v1.x + v1.y*v1.y + v1.z*v1.z + v1.w*v1.w;
        float s2 = v2.x + v2.y + v2.z + v2.w;
        float q2 = v2.x*v2.x + v2.y*v2.y + v2.z*v2.z + v2.w*v2.w;
        float s3 = v3.x + v3.y + v3.z + v3.w;
        float q3 = v3.x*v3.x + v3.y*v3.y + v3.z*v3.z + v3.w*v3.w;

        #pragma unroll
        for (int off = 16; off > 0; off >>= 1) {
            s0 += __shfl_xor_sync(0xffffffffu, s0, off);
            q0 += __shfl_xor_sync(0xffffffffu, q0, off);
            s1 += __shfl_xor_sync(0xffffffffu, s1, off);
            q1 += __shfl_xor_sync(0xffffffffu, q1, off);
            s2 += __shfl_xor_sync(0xffffffffu, s2, off);
            q2 += __shfl_xor_sync(0xffffffffu, q2, off);
            s3 += __shfl_xor_sync(0xffffffffu, s3, off);
            q3 += __shfl_xor_sync(0xffffffffu, q3, off);
        }

        const float m0 = s0 * (1.0f / C_Z);
        const float i0 = rsqrtf(q0 * (1.0f / C_Z) - m0 * m0 + EPS);
        const float m1 = s1 * (1.0f / C_Z);
        const float i1 = rsqrtf(q1 * (1.0f / C_Z) - m1 * m1 + EPS);
        const float m2 = s2 * (1.0f / C_Z);
        const float i2 = rsqrtf(q2 * (1.0f / C_Z) - m2 * m2 + EPS);
        const float m3 = s3 * (1.0f / C_Z);
        const float i3 = rsqrtf(q3 * (1.0f / C_Z) - m3 * m3 + EPS);

        const int b0 = __shfl_sync(0xffffffffu, mybin, r + 0);
        const int b1 = __shfl_sync(0xffffffffu, mybin, r + 1);
        const int b2 = __shfl_sync(0xffffffffu, mybin, r + 2);
        const int b3 = __shfl_sync(0xffffffffu, mybin, r + 3);

        const float4 f0 = *reinterpret_cast<const float4*>(ft + b0 * C_Z);
        const float4 f1 = *reinterpret_cast<const float4*>(ft + b1 * C_Z);
        const float4 f2 = *reinterpret_cast<const float4*>(ft + b2 * C_Z);
        const float4 f3 = *reinterpret_cast<const float4*>(ft + b3 * C_Z);

        float4 o;
        o.x = f0.x + (v0.x - m0) * i0 * g.x;
        o.y = f0.y + (v0.y - m0) * i0 * g.y;
        o.z = f0.z + (v0.z - m0) * i0 * g.z;
        o.w = f0.w + (v0.w - m0) * i0 * g.w;
        __stcs(obp + (r + 0) * 32, o);
        o.x = f1.x + (v1.x - m1) * i1 * g.x;
        o.y = f1.y + (v1.y - m1) * i1 * g.y;
        o.z = f1.z + (v1.z - m1) * i1 * g.z;
        o.w = f1.w + (v1.w - m1) * i1 * g.w;
        __stcs(obp + (r + 1) * 32, o);
        o.x = f2.x + (v2.x - m2) * i2 * g.x;
        o.y = f2.y + (v2.y - m2) * i2 * g.y;
        o.z = f2.z + (v2.z - m2) * i2 * g.z;
        o.w = f2.w + (v2.w - m2) * i2 * g.w;
        __stcs(obp + (r + 2) * 32, o);
        o.x = f3.x + (v3.x - m3) * i3 * g.x;
        o.y = f3.y + (v3.y - m3) * i3 * g.y;
        o.z = f3.z + (v3.z - m3) * i3 * g.z;
        o.w = f3.w + (v3.w - m3) * i3 * g.w;
        __stcs(obp + (r + 3) * 32, o);

        v0 = n0; v1 = n1; v2 = n2; v3 = n3;
    }
}

// ---------------------------------------------------------------------------
// Inputs (metadata order): m, z, x, w_lin, b_lin, g_m, be_m, g_z, be_z
// Output: concat(flatten(m_update), flatten(z_update))
// ---------------------------------------------------------------------------
extern "C" void kernel_launch(void* const* d_in, const int* in_sizes, int n_in,
                              void* d_out, int out_size)
{
    const float* m     = (const float*)d_in[0];
    const float* z     = (const float*)d_in[1];
    const float* x     = (const float*)d_in[2];
    const float* w_lin = (const float*)d_in[3];
    const float* b_lin = (const float*)d_in[4];
    const float* g_m   = (const float*)d_in[5];
    const float* be_m  = (const float*)d_in[6];
    const float* g_z   = (const float*)d_in[7];
    const float* be_z  = (const float*)d_in[8];

    float* out_m = (float*)d_out;
    float* out_z = out_m + (size_t)N_RES * C_M;

    fused_kernel<<<NZBLOCKS + NMBLOCKS, 256>>>(
        z, x, g_z, m, g_m, be_m, w_lin, b_lin, be_z, out_m, out_z);
}